// round 14
// baseline (speedup 1.0000x reference)
#include <cuda_runtime.h>
#include <cuda_fp16.h>
#include <cstdint>

// out = x @ (W*mask)^T, block-diagonal mask: 5 blocks of 819 + single col 4095.
// R14: HMMA fp16 GEMM (mainloop ~96% of legacy mma.sync roofline).
// Fix vs R13: proper stream-capture fork — sC must wait on an origin-stream
// event before launching (a side stream joins the capture graph only via such
// a wait; R13 launched on sC before any fork event -> capture failure).

#define H     4096
#define BLKW  819
#define NBLK  5
#define KPAD  832          // 13 * 64
#define NPAD  896          // 7 * 128
#define NCH   13
#define BK    64
#define BM    128
#define BN    128
#define NSTG  3

#define TILE_B   16384     // 128 rows * 128B
#define STAGE_B  (2 * TILE_B)
#define SMEM_B   (NSTG * STAGE_B)   // 98304

__device__ __align__(128) __half g_X16[(size_t)NBLK * 16384 * KPAD];
__device__ __align__(128) __half g_W16[(size_t)NBLK * NPAD  * KPAD];

__device__ __forceinline__ uint32_t s2u(const void* p) {
    uint32_t a;
    asm("{ .reg .u64 t; cvta.to.shared.u64 t, %1; cvt.u32.u64 %0, t; }"
        : "=r"(a) : "l"(p));
    return a;
}
__device__ __forceinline__ void cp16(uint32_t s, const void* g) {
    asm volatile("cp.async.cg.shared.global [%0], [%1], 16;"
                 :: "r"(s), "l"(g) : "memory");
}
__device__ __forceinline__ void ldsm4(uint32_t& r0, uint32_t& r1,
                                      uint32_t& r2, uint32_t& r3, uint32_t a) {
    asm volatile("ldmatrix.sync.aligned.m8n8.x4.shared.b16 {%0,%1,%2,%3}, [%4];"
                 : "=r"(r0), "=r"(r1), "=r"(r2), "=r"(r3) : "r"(a));
}
__device__ __forceinline__ void mma16816(float* c, const uint32_t* a,
                                         uint32_t b0, uint32_t b1) {
    asm volatile(
        "mma.sync.aligned.m16n8k16.row.col.f32.f16.f16.f32 "
        "{%0,%1,%2,%3}, {%4,%5,%6,%7}, {%8,%9}, {%0,%1,%2,%3};"
        : "+f"(c[0]), "+f"(c[1]), "+f"(c[2]), "+f"(c[3])
        : "r"(a[0]), "r"(a[1]), "r"(a[2]), "r"(a[3]), "r"(b0), "r"(b1));
}

// ---------------- fp32 -> fp16 padded per-block layouts ---------------------
__global__ void convert_x_kernel(const float* __restrict__ x, int M, int b) {
    const int t = blockIdx.x * blockDim.x + threadIdx.x;   // [0, M*KPAD/4)
    const int m  = t / (KPAD / 4);
    const int k4 = (t % (KPAD / 4)) * 4;
    const float* sp = x + (size_t)m * H + b * BLKW + k4;
    float v[4];
    #pragma unroll
    for (int j = 0; j < 4; j++) v[j] = (k4 + j < BLKW) ? sp[j] : 0.0f;
    __half2 h0 = __halves2half2(__float2half_rn(v[0]), __float2half_rn(v[1]));
    __half2 h1 = __halves2half2(__float2half_rn(v[2]), __float2half_rn(v[3]));
    const size_t dst = ((size_t)b * M + m) * KPAD + k4;
    *(__half2*)(g_X16 + dst)     = h0;
    *(__half2*)(g_X16 + dst + 2) = h1;
}

__global__ void convert_w_kernel(const float* __restrict__ W) {
    const int b = blockIdx.y;
    const int t = blockIdx.x * blockDim.x + threadIdx.x;   // [0, NPAD*KPAD/4)
    const int n  = t / (KPAD / 4);
    const int k4 = (t % (KPAD / 4)) * 4;
    const float* sp = W + (size_t)(b * BLKW + n) * H + b * BLKW + k4;
    float v[4];
    #pragma unroll
    for (int j = 0; j < 4; j++)
        v[j] = (n < BLKW && k4 + j < BLKW) ? sp[j] : 0.0f;
    __half2 h0 = __halves2half2(__float2half_rn(v[0]), __float2half_rn(v[1]));
    __half2 h1 = __halves2half2(__float2half_rn(v[2]), __float2half_rn(v[3]));
    const size_t dst = ((size_t)b * NPAD + n) * KPAD + k4;
    *(__half2*)(g_W16 + dst)     = h0;
    *(__half2*)(g_W16 + dst + 2) = h1;
}

// ---------------- main HMMA GEMM (one diagonal block per launch) ------------
__global__ void __maxnreg__(116)
gemm_kernel(float* __restrict__ out, int M, int blk) {
    extern __shared__ __align__(1024) char smem[];
    const uint32_t sb = s2u(smem);
    const int tid = threadIdx.x;
    const int ntile = blockIdx.x;          // 0..6
    const int m0    = blockIdx.y * BM;

    const int w  = tid >> 5, l = tid & 31;
    const int wm = (w & 3) * 32;
    const int wn = (w >> 2) * 64;

    const bool active = !(ntile == 6 && wn == 64);

    const __half* gA = g_X16 + ((size_t)blk * M    + m0)          * KPAD;
    const __half* gB = g_W16 + ((size_t)blk * NPAD + ntile * 128) * KPAD;

    const int lrow = tid >> 1;

    auto load_stage = [&](int s, int kc) {
        const uint32_t st = sb + s * STAGE_B;
        const int c0 = (tid & 1) * 4;
        const __half* ga = gA + (size_t)lrow * KPAD + kc;
        const __half* gb = gB + (size_t)lrow * KPAD + kc;
        const uint32_t rbase = lrow * 128;
        const uint32_t rx    = (lrow & 7) << 4;
        #pragma unroll
        for (int j = 0; j < 4; j++) {
            const int ch = c0 + j;
            const uint32_t so = rbase + ((uint32_t)(ch << 4) ^ rx);
            cp16(st + so,          ga + ch * 8);
            cp16(st + TILE_B + so, gb + ch * 8);
        }
        asm volatile("cp.async.commit_group;" ::: "memory");
    };

    uint32_t aBase[2], aXor[2];
    #pragma unroll
    for (int mt = 0; mt < 2; mt++) {
        const int ml = wm + mt * 16 + (l & 7) + ((l >> 3) & 1) * 8;
        aBase[mt] = ml * 128;
        aXor[mt]  = (ml & 7) << 4;
    }
    const uint32_t kA = ((l >> 4) & 1) << 4;

    uint32_t bBase[4], bXor[4];
    const int g = l >> 3;
    #pragma unroll
    for (int q = 0; q < 4; q++) {
        const int nl = wn + q * 16 + ((g >> 1) << 3) + (l & 7);
        bBase[q] = TILE_B + nl * 128;
        bXor[q]  = (nl & 7) << 4;
    }
    const uint32_t kB = (g & 1) << 4;

    float c[2][8][4];
    #pragma unroll
    for (int mt = 0; mt < 2; mt++)
        #pragma unroll
        for (int nt = 0; nt < 8; nt++)
            #pragma unroll
            for (int r = 0; r < 4; r++) c[mt][nt][r] = 0.0f;

    load_stage(0, 0);
    load_stage(1, BK);

    for (int i = 0; i < NCH; i++) {
        asm volatile("cp.async.wait_group 1;" ::: "memory");
        __syncthreads();

        if (active) {
            const uint32_t st = sb + (i % NSTG) * STAGE_B;
            #pragma unroll
            for (int ks = 0; ks < 4; ks++) {
                const uint32_t kso = ks * 32;
                uint32_t a[2][4];
                #pragma unroll
                for (int mt = 0; mt < 2; mt++)
                    ldsm4(a[mt][0], a[mt][1], a[mt][2], a[mt][3],
                          st + aBase[mt] + ((kso + kA) ^ aXor[mt]));
                uint32_t b[4][4];
                #pragma unroll
                for (int q = 0; q < 4; q++)
                    ldsm4(b[q][0], b[q][1], b[q][2], b[q][3],
                          st + bBase[q] + ((kso + kB) ^ bXor[q]));
                #pragma unroll
                for (int mt = 0; mt < 2; mt++)
                    #pragma unroll
                    for (int nt = 0; nt < 8; nt++) {
                        const int q = nt >> 1;
                        if (nt & 1) mma16816(c[mt][nt], a[mt], b[q][2], b[q][3]);
                        else        mma16816(c[mt][nt], a[mt], b[q][0], b[q][1]);
                    }
            }
        }

        const int nx = i + 2;
        if (nx < NCH) load_stage(nx % NSTG, nx * BK);
        else asm volatile("cp.async.commit_group;" ::: "memory");
    }

    // ---- epilogue: scalar STG.32 (colb may be odd)
    const int lim  = BLKW - ntile * 128;
    const size_t colb = (size_t)blk * BLKW + ntile * 128;
    const int l2 = l >> 2, l3 = (l & 3) << 1;
    if (active) {
        #pragma unroll
        for (int mt = 0; mt < 2; mt++) {
            const int rbase = m0 + wm + mt * 16 + l2;
            float* o0 = out + (size_t)rbase * H + colb;
            float* o1 = o0 + (size_t)8 * H;
            #pragma unroll
            for (int nt = 0; nt < 8; nt++) {
                const int col = wn + nt * 8 + l3;
                if (col < lim) {
                    o0[col] = c[mt][nt][0];
                    o1[col] = c[mt][nt][2];
                }
                if (col + 1 < lim) {
                    o0[col + 1] = c[mt][nt][1];
                    o1[col + 1] = c[mt][nt][3];
                }
            }
        }
    }
}

__global__ void last_col_kernel(const float* __restrict__ x,
                                const float* __restrict__ W,
                                float* __restrict__ out, int M) {
    const int m = blockIdx.x * blockDim.x + threadIdx.x;
    if (m < M) {
        const float w = __ldg(&W[(size_t)4095 * H + 4095]);
        out[(size_t)m * H + 4095] = x[(size_t)m * H + 4095] * w;
    }
}

extern "C" void kernel_launch(void* const* d_in, const int* in_sizes, int n_in,
                              void* d_out, int out_size) {
    const float* x = (const float*)d_in[0];
    const float* W = (const float*)d_in[1];
    float* out = (float*)d_out;
    const int M = in_sizes[0] / H;   // 16384

    static cudaStream_t sA = nullptr, sB = nullptr, sC = nullptr;
    static cudaEvent_t root, fx[NBLK], ew, eC, gA_done, gB_done;
    if (!sA) {
        cudaStreamCreateWithFlags(&sA, cudaStreamNonBlocking);
        cudaStreamCreateWithFlags(&sB, cudaStreamNonBlocking);
        cudaStreamCreateWithFlags(&sC, cudaStreamNonBlocking);
        cudaEventCreateWithFlags(&root, cudaEventDisableTiming);
        for (int b = 0; b < NBLK; b++)
            cudaEventCreateWithFlags(&fx[b], cudaEventDisableTiming);
        cudaEventCreateWithFlags(&ew, cudaEventDisableTiming);
        cudaEventCreateWithFlags(&eC, cudaEventDisableTiming);
        cudaEventCreateWithFlags(&gA_done, cudaEventDisableTiming);
        cudaEventCreateWithFlags(&gB_done, cudaEventDisableTiming);
        cudaFuncSetAttribute(gemm_kernel,
                             cudaFuncAttributeMaxDynamicSharedMemorySize, SMEM_B);
    }

    // fork point on the capturing origin stream: side streams join capture
    // only by waiting on an origin-recorded event.
    cudaEventRecord(root, 0);
    cudaStreamWaitEvent(sC, root, 0);
    cudaStreamWaitEvent(sA, root, 0);
    cudaStreamWaitEvent(sB, root, 0);

    // sC: W convert + independent last-col column
    convert_w_kernel<<<dim3((NPAD * (KPAD / 4)) / 256, NBLK), 256, 0, sC>>>(W);
    cudaEventRecord(ew, sC);
    last_col_kernel<<<(M + 255) / 256, 256, 0, sC>>>(x, W, out, M);
    cudaEventRecord(eC, sC);

    // origin: per-block x converts (cx0 starts at t=0)
    for (int b = 0; b < NBLK; b++) {
        convert_x_kernel<<<(M * (KPAD / 4)) / 256, 256>>>(x, M, b);
        cudaEventRecord(fx[b], 0);
    }

    // per-block GEMMs on two forked streams, gated on cw + cx(b)
    dim3 grid(NPAD / BN, M / BM);
    cudaStreamWaitEvent(sA, ew, 0);
    cudaStreamWaitEvent(sB, ew, 0);
    for (int b = 0; b < NBLK; b++) {
        cudaStream_t s = (b & 1) ? sB : sA;
        cudaStreamWaitEvent(s, fx[b], 0);
        gemm_kernel<<<grid, 256, SMEM_B, s>>>(out, M, b);
    }
    cudaEventRecord(gA_done, sA);
    cudaEventRecord(gB_done, sB);

    // join everything back to origin stream
    cudaStreamWaitEvent(0, gA_done, 0);
    cudaStreamWaitEvent(0, gB_done, 0);
    cudaStreamWaitEvent(0, eC, 0);
}